// round 1
// baseline (speedup 1.0000x reference)
#include <cuda_runtime.h>
#include <cstdint>

#define H      128
#define NHEAD  8
#define TE     32
#define N_MAX  50000
#define E_MAX  800000
#define NRELMX 64
#define GPAD   36   // padded stride for transposed g tile (multiple of 4 for LDS.128)

// ---------------- scratch (static device globals; no runtime allocation) ----
__device__ float    g_Q   [N_MAX * H];
__device__ float    g_S1  [N_MAX * H];
__device__ float    g_R2x [NRELMX * H];
__device__ float    g_Vbuf[(size_t)E_MAX * H];     // ~410 MB
__device__ float    g_Sbuf[E_MAX * NHEAD];
__device__ unsigned g_segmax[N_MAX * NHEAD];       // order-preserving uint encoding
__device__ float    g_denom [N_MAX * NHEAD];

// order-preserving float<->uint transform for atomicMax
__device__ __forceinline__ unsigned enc_f(float f) {
    int b = __float_as_int(f);
    return (b >= 0) ? ((unsigned)b | 0x80000000u) : ~(unsigned)b;
}
__device__ __forceinline__ float dec_f(unsigned u) {
    return (u & 0x80000000u) ? __uint_as_float(u & 0x7FFFFFFFu) : __uint_as_float(~u);
}

// ---------------- init: zero out, denom, segmax ----------------------------
__global__ void k_init(float* __restrict__ out, int N, int outElems) {
    int i = blockIdx.x * blockDim.x + threadIdx.x;
    int stride = gridDim.x * blockDim.x;
    for (int idx = i; idx < outElems; idx += stride) out[idx] = 0.f;
    for (int idx = i; idx < N * NHEAD; idx += stride) {
        g_denom[idx] = 0.f;
        g_segmax[idx] = 0u;   // below enc_f(-inf); always overwritten before read
    }
}

// ---------------- R2x[r] = rel_table[r] @ W1[128:256] + W1[256] ------------
__global__ void k_rel(const float* __restrict__ rel, const float* __restrict__ W1) {
    int r = blockIdx.x, j = threadIdx.x;
    float acc = W1[256 * H + j];
    for (int i = 0; i < H; i++)
        acc += rel[r * H + i] * W1[(H + i) * H + j];
    g_R2x[r * H + j] = acc;
}

// ---------------- node precompute: Q = x@Wq+bq, S1 = x@W1[:128] ------------
__global__ void __launch_bounds__(128) k_node(
    const float* __restrict__ x, const float* __restrict__ Wq,
    const float* __restrict__ bq, const float* __restrict__ W1, int N)
{
    __shared__ float xs[TE][H];
    int n0 = blockIdx.x * TE;
    int j = threadIdx.x;
    int cnt = min(TE, N - n0);
    for (int e = 0; e < cnt; e++) xs[e][j] = x[(size_t)(n0 + e) * H + j];
    __syncthreads();
    float aq[TE], as_[TE];
#pragma unroll
    for (int e = 0; e < TE; e++) { aq[e] = 0.f; as_[e] = 0.f; }
    for (int kk = 0; kk < H; kk++) {
        float wq = Wq[kk * H + j];
        float w1 = W1[kk * H + j];
#pragma unroll
        for (int e = 0; e < TE; e++) {
            float xv = xs[e][kk];
            aq[e]  = fmaf(xv, wq, aq[e]);
            as_[e] = fmaf(xv, w1, as_[e]);
        }
    }
    float bqj = bq[j];
    for (int e = 0; e < cnt; e++) {
        g_Q [(n0 + e) * H + j] = aq[e] + bqj;
        g_S1[(n0 + e) * H + j] = as_[e];
    }
}

// ---------------- fused edge kernel ----------------------------------------
// per 32-edge tile: time gate -> h -> dw -> g@(Wk|Wv) via packed fp32x2 FMA
// -> scores (+segmax atomicMax) + V write
__global__ void __launch_bounds__(128) k_edge(
    const float* __restrict__ x, const float* __restrict__ ts,
    const int* __restrict__ src, const int* __restrict__ dst, const int* __restrict__ et,
    const float* __restrict__ etime, const float* __restrict__ rel,
    const float* __restrict__ Wk, const float* __restrict__ bk,
    const float* __restrict__ Wv, const float* __restrict__ bv,
    const float* __restrict__ b1, const float* __restrict__ W2,
    const float* __restrict__ b2, const float* __restrict__ tcp, int E)
{
    __shared__ __align__(16) float g_t[H * GPAD];    // g transposed: g_t[kk*GPAD+e]
    __shared__ float p_s[TE][H];
    __shared__ int   src_s[TE], dst_s[TE], et_s[TE];
    __shared__ float tm_s[TE], s_s[TE];

    int e0 = blockIdx.x * TE;
    int j = threadIdx.x;
    int cnt = min(TE, E - e0);

    if (j < TE) {
        if (j < cnt) {
            int ee = e0 + j;
            int d = dst[ee];
            src_s[j] = src[ee]; dst_s[j] = d; et_s[j] = et[ee];
            float inv_tc = 1.f / (fabsf(tcp[0]) + 1e-9f);
            float dt = (ts[d] - etime[ee]) * inv_tc;
            tm_s[j] = 1.f / (1.f + expf(-dt));
        } else {
            src_s[j] = 0; dst_s[j] = 0; et_s[j] = 0; tm_s[j] = 0.f;
        }
    }
    __syncthreads();

    // phase 1: g = x[src] * rel[et]; p = relu(S1+tm*R2x+b1)*W2
    float b1j = b1[j], w2j = W2[j];
#pragma unroll 4
    for (int e = 0; e < TE; e++) {
        float g = 0.f, p = 0.f;
        if (e < cnt) {
            int sn = src_s[e], rr = et_s[e];
            float xv = x[(size_t)sn * H + j];
            float rv = rel[rr * H + j];
            g = xv * rv;
            float h = fmaf(tm_s[e], g_R2x[rr * H + j], g_S1[sn * H + j] + b1j);
            h = fmaxf(h, 0.f);
            p = h * w2j;
        }
        g_t[j * GPAD + e] = g;
        p_s[e][j] = p;
    }
    __syncthreads();

    // phase 2: dw = sigmoid(h.W2 + b2); s = tm*dw
    {
        int wid = j >> 5, lane = j & 31;
        float b2v = b2[0];
        for (int i = 0; i < 8; i++) {
            int e = wid * 8 + i;
            float v = p_s[e][lane] + p_s[e][lane + 32] + p_s[e][lane + 64] + p_s[e][lane + 96];
            v += __shfl_xor_sync(0xFFFFFFFFu, v, 16);
            v += __shfl_xor_sync(0xFFFFFFFFu, v, 8);
            v += __shfl_xor_sync(0xFFFFFFFFu, v, 4);
            v += __shfl_xor_sync(0xFFFFFFFFu, v, 2);
            v += __shfl_xor_sync(0xFFFFFFFFu, v, 1);
            if (lane == 0) {
                float dw = 1.f / (1.f + expf(-(v + b2v)));
                s_s[e] = tm_s[e] * dw;
            }
        }
    }
    __syncthreads();

    // phase 3: packed-fp32 GEMM: (g @ Wk), (g @ Wv), 32 edges x col j
    unsigned long long ak[TE / 2], av[TE / 2];
#pragma unroll
    for (int i = 0; i < TE / 2; i++) { ak[i] = 0ull; av[i] = 0ull; }
    for (int kk = 0; kk < H; kk++) {
        float wk = Wk[kk * H + j];
        float wv = Wv[kk * H + j];
        unsigned long long wk2, wv2;
        asm("mov.b64 %0, {%1,%1};" : "=l"(wk2) : "f"(wk));
        asm("mov.b64 %0, {%1,%1};" : "=l"(wv2) : "f"(wv));
        const ulonglong2* gp = (const ulonglong2*)(&g_t[kk * GPAD]);
#pragma unroll
        for (int q4 = 0; q4 < TE / 4; q4++) {
            ulonglong2 gg = gp[q4];
            asm("fma.rn.f32x2 %0, %1, %2, %0;" : "+l"(ak[q4 * 2])     : "l"(gg.x), "l"(wk2));
            asm("fma.rn.f32x2 %0, %1, %2, %0;" : "+l"(ak[q4 * 2 + 1]) : "l"(gg.y), "l"(wk2));
            asm("fma.rn.f32x2 %0, %1, %2, %0;" : "+l"(av[q4 * 2])     : "l"(gg.x), "l"(wv2));
            asm("fma.rn.f32x2 %0, %1, %2, %0;" : "+l"(av[q4 * 2 + 1]) : "l"(gg.y), "l"(wv2));
        }
    }

    // phase 4: scores (16-lane head reduction), segmax, V store
    float bkj = bk[j], bvj = bv[j];
    int head = j >> 4;
#pragma unroll
    for (int e = 0; e < TE; e++) {
        float rawk = (e & 1) ? __uint_as_float((unsigned)(ak[e >> 1] >> 32))
                             : __uint_as_float((unsigned)(ak[e >> 1] & 0xFFFFFFFFull));
        float rawv = (e & 1) ? __uint_as_float((unsigned)(av[e >> 1] >> 32))
                             : __uint_as_float((unsigned)(av[e >> 1] & 0xFFFFFFFFull));
        bool valid = (e < cnt);
        float se = s_s[e];
        float kj = fmaf(rawk, se, bkj);
        float vj = fmaf(rawv, se, bvj);
        float qv = valid ? g_Q[dst_s[e] * H + j] : 0.f;
        float prod = qv * kj;
        prod += __shfl_xor_sync(0xFFFFFFFFu, prod, 8);
        prod += __shfl_xor_sync(0xFFFFFFFFu, prod, 4);
        prod += __shfl_xor_sync(0xFFFFFFFFu, prod, 2);
        prod += __shfl_xor_sync(0xFFFFFFFFu, prod, 1);
        if (valid) {
            __stcs(&g_Vbuf[(size_t)(e0 + e) * H + j], vj);
            if ((j & 15) == 0) {
                float sc = prod * 0.25f;   // / sqrt(16)
                g_Sbuf[(e0 + e) * NHEAD + head] = sc;
                atomicMax(&g_segmax[dst_s[e] * NHEAD + head], enc_f(sc));
            }
        }
    }
}

// ---------------- pass 2: exp, denom, weighted V scatter (v4 RED) ----------
__global__ void k_scatter(const int* __restrict__ dst, float* __restrict__ out, int E)
{
    int gw = (int)((blockIdx.x * blockDim.x + threadIdx.x) >> 5);
    int lane = threadIdx.x & 31;
    if (gw >= E) return;
    int e = gw;
    int d = dst[e];
    int h = lane >> 2;
    float s = g_Sbuf[e * NHEAD + h];
    float m = dec_f(g_segmax[d * NHEAD + h]);
    float w = expf(s - m);
    if ((lane & 3) == 0) atomicAdd(&g_denom[d * NHEAD + h], w);
    const float4* vp = (const float4*)(&g_Vbuf[(size_t)e * H]);
    float4 v = __ldcs(&vp[lane]);
    float* op = out + (size_t)d * H + lane * 4;
    asm volatile("red.global.add.v4.f32 [%0], {%1,%2,%3,%4};"
                 :: "l"(op), "f"(w * v.x), "f"(w * v.y), "f"(w * v.z), "f"(w * v.w)
                 : "memory");
}

// ---------------- pass 3: normalize by denom -------------------------------
__global__ void k_norm(float* __restrict__ out, int N)
{
    int idx = blockIdx.x * blockDim.x + threadIdx.x;
    if (idx >= N * H) return;
    int n = idx >> 7, jj = idx & (H - 1);
    float dnm = g_denom[n * NHEAD + (jj >> 4)];
    float v = out[idx];
    out[idx] = (dnm > 0.f) ? v / dnm : 0.f;
}

// ---------------- launch ---------------------------------------------------
extern "C" void kernel_launch(void* const* d_in, const int* in_sizes, int n_in,
                              void* d_out, int out_size)
{
    const float* x     = (const float*)d_in[0];
    const float* ts    = (const float*)d_in[1];
    const int*   src   = (const int*)  d_in[2];
    const int*   dst   = (const int*)  d_in[3];
    const int*   etyp  = (const int*)  d_in[4];
    const float* etime = (const float*)d_in[5];
    const float* rel   = (const float*)d_in[6];
    const float* Wq    = (const float*)d_in[7];
    const float* bq    = (const float*)d_in[8];
    const float* Wk    = (const float*)d_in[9];
    const float* bk    = (const float*)d_in[10];
    const float* Wv    = (const float*)d_in[11];
    const float* bv    = (const float*)d_in[12];
    const float* W1    = (const float*)d_in[13];
    const float* b1    = (const float*)d_in[14];
    const float* W2    = (const float*)d_in[15];
    const float* b2    = (const float*)d_in[16];
    const float* tcp   = (const float*)d_in[17];

    int N    = in_sizes[0] / H;
    int E    = in_sizes[2];
    int NREL = in_sizes[6] / H;
    float* out = (float*)d_out;

    k_init<<<2048, 256>>>(out, N, out_size);
    k_rel <<<NREL, H>>>(rel, W1);
    k_node<<<(N + TE - 1) / TE, H>>>(x, Wq, bq, W1, N);
    k_edge<<<(E + TE - 1) / TE, H>>>(x, ts, src, dst, etyp, etime, rel,
                                     Wk, bk, Wv, bv, b1, W2, b2, tcp, E);
    k_scatter<<<(E + 7) / 8, 256>>>(dst, out, E);
    k_norm<<<(N * H + 255) / 256, 256>>>(out, N);
}

// round 4
// speedup vs baseline: 1.3836x; 1.3836x over previous
#include <cuda_runtime.h>
#include <cuda_bf16.h>
#include <cstdint>

#define H       128
#define NHEAD   8
#define N_MAX   50000
#define E_MAX   800000
#define NRELMX  64
#define TEN     32
#define GPAD    36
#define TILE_E  128
#define NT      512

// ---------------- global scratch -------------------------------------------
__device__ float g_Q  [N_MAX * H];
__device__ float g_S1 [N_MAX * H];
__device__ float g_R2x[NRELMX * H];
__device__ float g_denom[N_MAX * NHEAD];
__device__ __nv_bfloat16 g_Bhi[256 * H];   // [n][k], XOR-swizzled rows of 256B
__device__ __nv_bfloat16 g_Blo[256 * H];

// ---------------- smem layout ----------------------------------------------
#define OFF_BHI   0
#define OFF_BLO   65536
#define OFF_AHI   131072
#define OFF_ALO   163840
#define OFF_KV    131072   // aliases A region (used after GEMM)
#define OFF_BK    196608
#define OFF_BV    197120
#define OFF_B1    197632
#define OFF_W2    198144
#define OFF_DST   198656
#define OFF_SRC   199168
#define OFF_ET    199680
#define OFF_TM    200192
#define OFF_SS    200704
#define OFF_WS    201216   // 128*8 floats
#define OFF_HP    205312   // 512 floats
#define SMEM_EDGE 207360

// ---------------- helpers --------------------------------------------------
__device__ __forceinline__ uint32_t s2u(const void* p) {
    uint32_t a;
    asm("{ .reg .u64 t; cvta.to.shared.u64 t, %1; cvt.u32.u64 %0, t; }" : "=r"(a) : "l"(p));
    return a;
}
__device__ __forceinline__ void ldsm4(uint32_t* r, uint32_t addr) {
    asm volatile("ldmatrix.sync.aligned.m8n8.x4.shared.b16 {%0,%1,%2,%3}, [%4];"
                 : "=r"(r[0]), "=r"(r[1]), "=r"(r[2]), "=r"(r[3]) : "r"(addr));
}
__device__ __forceinline__ void ldsm2(uint32_t* r, uint32_t addr) {
    asm volatile("ldmatrix.sync.aligned.m8n8.x2.shared.b16 {%0,%1}, [%2];"
                 : "=r"(r[0]), "=r"(r[1]) : "r"(addr));
}
__device__ __forceinline__ void mma16816(float* c, const uint32_t* a, const uint32_t* b) {
    asm volatile(
        "mma.sync.aligned.m16n8k16.row.col.f32.bf16.bf16.f32 "
        "{%0,%1,%2,%3}, {%4,%5,%6,%7}, {%8,%9}, {%0,%1,%2,%3};"
        : "+f"(c[0]), "+f"(c[1]), "+f"(c[2]), "+f"(c[3])
        : "r"(a[0]), "r"(a[1]), "r"(a[2]), "r"(a[3]), "r"(b[0]), "r"(b[1]));
}

// ---------------- init -----------------------------------------------------
__global__ void k_init(float* __restrict__ out, int N, int outElems) {
    int i = blockIdx.x * blockDim.x + threadIdx.x;
    int stride = gridDim.x * blockDim.x;
    for (int idx = i; idx < outElems; idx += stride) out[idx] = 0.f;
    for (int idx = i; idx < N * NHEAD; idx += stride) g_denom[idx] = 0.f;
}

// ---------------- R2x[r] = rel[r] @ W1[128:256] + W1[256] ------------------
__global__ void k_rel(const float* __restrict__ rel, const float* __restrict__ W1) {
    int r = blockIdx.x, j = threadIdx.x;
    float acc = W1[256 * H + j];
    for (int i = 0; i < H; i++)
        acc += rel[r * H + i] * W1[(H + i) * H + j];
    g_R2x[r * H + j] = acc;
}

// ---------------- weight images: BT[n][k] = W[k][n], bf16 hi/lo ------------
__global__ void k_prepw(const float* __restrict__ Wk, const float* __restrict__ Wv) {
    int n = blockIdx.x, k = threadIdx.x;
    float w = (n < H) ? Wk[k * H + n] : Wv[k * H + (n - H)];
    __nv_bfloat16 hi = __float2bfloat16(w);
    float lo = w - __bfloat162float(hi);
    unsigned kb = (unsigned)k * 2u;
    unsigned phys = (unsigned)n * 256u + (kb ^ ((unsigned)(n & 7) << 4));
    *(__nv_bfloat16*)((char*)g_Bhi + phys) = hi;
    *(__nv_bfloat16*)((char*)g_Blo + phys) = __float2bfloat16(lo);
}

// ---------------- node precompute: Q = x@Wq+bq, S1 = x@W1[:128] ------------
__global__ void __launch_bounds__(128) k_node(
    const float* __restrict__ x, const float* __restrict__ Wq,
    const float* __restrict__ bq, const float* __restrict__ W1, int N)
{
    __shared__ __align__(16) float xt[H * GPAD];
    int n0 = blockIdx.x * TEN;
    int j = threadIdx.x;
    int cnt = min(TEN, N - n0);
    for (int e = 0; e < TEN; e++)
        xt[j * GPAD + e] = (e < cnt) ? x[(size_t)(n0 + e) * H + j] : 0.f;
    __syncthreads();

    unsigned long long aq[TEN / 2], as_[TEN / 2];
#pragma unroll
    for (int i = 0; i < TEN / 2; i++) { aq[i] = 0ull; as_[i] = 0ull; }
    for (int kk = 0; kk < H; kk++) {
        float wq = Wq[kk * H + j];
        float w1 = W1[kk * H + j];
        unsigned long long wq2, w12;
        asm("mov.b64 %0, {%1,%1};" : "=l"(wq2) : "f"(wq));
        asm("mov.b64 %0, {%1,%1};" : "=l"(w12) : "f"(w1));
        const ulonglong2* gp = (const ulonglong2*)(&xt[kk * GPAD]);
#pragma unroll
        for (int q4 = 0; q4 < TEN / 4; q4++) {
            ulonglong2 gg = gp[q4];
            asm("fma.rn.f32x2 %0, %1, %2, %0;" : "+l"(aq[q4 * 2])      : "l"(gg.x), "l"(wq2));
            asm("fma.rn.f32x2 %0, %1, %2, %0;" : "+l"(aq[q4 * 2 + 1])  : "l"(gg.y), "l"(wq2));
            asm("fma.rn.f32x2 %0, %1, %2, %0;" : "+l"(as_[q4 * 2])     : "l"(gg.x), "l"(w12));
            asm("fma.rn.f32x2 %0, %1, %2, %0;" : "+l"(as_[q4 * 2 + 1]) : "l"(gg.y), "l"(w12));
        }
    }
    float bqj = bq[j];
    for (int e = 0; e < cnt; e++) {
        float vq = (e & 1) ? __uint_as_float((unsigned)(aq[e >> 1] >> 32))
                           : __uint_as_float((unsigned)(aq[e >> 1] & 0xFFFFFFFFull));
        float vs = (e & 1) ? __uint_as_float((unsigned)(as_[e >> 1] >> 32))
                           : __uint_as_float((unsigned)(as_[e >> 1] & 0xFFFFFFFFull));
        g_Q [(n0 + e) * H + j] = vq + bqj;
        g_S1[(n0 + e) * H + j] = vs;
    }
}

// ---------------- persistent fused edge kernel (mma.sync bf16 3-pass) ------
__global__ void __launch_bounds__(NT, 1) k_edge_mma(
    const float* __restrict__ x, const float* __restrict__ ts,
    const int* __restrict__ src, const int* __restrict__ dst, const int* __restrict__ et,
    const float* __restrict__ etime, const float* __restrict__ rel,
    const float* __restrict__ bk, const float* __restrict__ bv,
    const float* __restrict__ b1, const float* __restrict__ W2,
    const float* __restrict__ b2, const float* __restrict__ tcp,
    float* __restrict__ out, int E, int ntiles)
{
    extern __shared__ __align__(1024) char smc[];
    uint32_t smb = s2u(smc);
    int tid = threadIdx.x, wid = tid >> 5, lane = tid & 31;

    float* bk_s  = (float*)(smc + OFF_BK);
    float* bv_s  = (float*)(smc + OFF_BV);
    float* b1_s  = (float*)(smc + OFF_B1);
    float* w2_s  = (float*)(smc + OFF_W2);
    int*   dst_s = (int*)  (smc + OFF_DST);
    int*   src_s = (int*)  (smc + OFF_SRC);
    int*   et_s  = (int*)  (smc + OFF_ET);
    float* tm_s  = (float*)(smc + OFF_TM);
    float* ss_s  = (float*)(smc + OFF_SS);
    float* w_sm  = (float*)(smc + OFF_WS);
    float* hp_s  = (float*)(smc + OFF_HP);

    // stage B images into smem once
    {
        float4* d0 = (float4*)(smc + OFF_BHI);
        float4* d1 = (float4*)(smc + OFF_BLO);
        const float4* s0 = (const float4*)g_Bhi;
        const float4* s1 = (const float4*)g_Blo;
        for (int i = tid; i < 4096; i += NT) d0[i] = s0[i];
        for (int i = tid; i < 4096; i += NT) d1[i] = s1[i];
    }
    if (tid < H) { bk_s[tid] = bk[tid]; bv_s[tid] = bv[tid]; b1_s[tid] = b1[tid]; w2_s[tid] = W2[tid]; }
    __syncthreads();

    float inv_tc = 1.f / (fabsf(tcp[0]) + 1e-9f);
    float b2v = b2[0];

    // per-warp constant fragment addressing
    int n0k = wid * 8;          // K columns
    int n0v = 128 + wid * 8;    // V columns
    int rb = lane & 7, mb = (lane >> 3) & 1;
    uint32_t bXor = (uint32_t)rb << 4;
    uint32_t bRowK = smb + OFF_BHI + (uint32_t)(n0k + rb) * 256u;
    uint32_t bRowV = smb + OFF_BHI + (uint32_t)(n0v + rb) * 256u;
    uint32_t bLoRowK = bRowK + (OFF_BLO - OFF_BHI);
    uint32_t bLoRowV = bRowV + (OFF_BLO - OFF_BHI);
    int ra = lane & 7, ha = (lane >> 3) & 1, kh = lane >> 4;
    uint32_t aRowLoc = (uint32_t)(ha * 8 + ra) * 256u;
    uint32_t aXor = (uint32_t)ra << 4;
    uint32_t aKh = (uint32_t)(kh * 16);
    int r4 = lane >> 2, c2 = (lane & 3) * 2;

    for (int t = blockIdx.x; t < ntiles; t += gridDim.x) {
        int e0 = t * TILE_E;
        int cnt = min(TILE_E, E - e0);

        // ---- edge meta + time gate ----
        if (tid < TILE_E) {
            float tm = 0.f;
            if (tid < cnt) {
                int ee = e0 + tid;
                int d = dst[ee];
                src_s[tid] = src[ee]; dst_s[tid] = d; et_s[tid] = et[ee];
                float dt = (ts[d] - etime[ee]) * inv_tc;
                tm = 1.f / (1.f + expf(-dt));
            } else { src_s[tid] = 0; dst_s[tid] = 0; et_s[tid] = 0; }
            tm_s[tid] = tm;
        }
        __syncthreads();

        // ---- gather: g = x[src]*rel[et] -> bf16 hi/lo A tile + gating dot ----
        {
            int e = tid >> 2, qq = tid & 3;
            int sn = src_s[e], rr = et_s[e];
            float tme = tm_s[e];
            const float4* xp  = (const float4*)(x     + (size_t)sn * H) + qq * 8;
            const float4* rp  = (const float4*)(rel   + (size_t)rr * H) + qq * 8;
            const float4* sp  = (const float4*)(g_S1  + (size_t)sn * H) + qq * 8;
            const float4* r2p = (const float4*)(g_R2x + (size_t)rr * H) + qq * 8;
            char* Ahi = smc + OFF_AHI + e * 256;
            char* Alo = smc + OFF_ALO + e * 256;
            unsigned xr = (unsigned)(e & 7) << 4;
            float hacc = 0.f;
#pragma unroll
            for (int i = 0; i < 8; i++) {
                float4 xv = __ldg(xp + i), rv = __ldg(rp + i);
                float4 s1 = __ldg(sp + i), r2 = __ldg(r2p + i);
                int col = qq * 32 + i * 4;
                float g0 = xv.x * rv.x, g1 = xv.y * rv.y, g2 = xv.z * rv.z, g3 = xv.w * rv.w;
                hacc += fmaxf(fmaf(tme, r2.x, s1.x + b1_s[col + 0]), 0.f) * w2_s[col + 0];
                hacc += fmaxf(fmaf(tme, r2.y, s1.y + b1_s[col + 1]), 0.f) * w2_s[col + 1];
                hacc += fmaxf(fmaf(tme, r2.z, s1.z + b1_s[col + 2]), 0.f) * w2_s[col + 2];
                hacc += fmaxf(fmaf(tme, r2.w, s1.w + b1_s[col + 3]), 0.f) * w2_s[col + 3];
                __nv_bfloat162 h01 = __floats2bfloat162_rn(g0, g1);
                __nv_bfloat162 h23 = __floats2bfloat162_rn(g2, g3);
                float l0 = g0 - __bfloat162float(h01.x);
                float l1 = g1 - __bfloat162float(h01.y);
                float l2 = g2 - __bfloat162float(h23.x);
                float l3 = g3 - __bfloat162float(h23.y);
                __nv_bfloat162 l01 = __floats2bfloat162_rn(l0, l1);
                __nv_bfloat162 l23 = __floats2bfloat162_rn(l2, l3);
                unsigned kb = (unsigned)(qq * 64 + i * 8);
                uint2 uh; uh.x = *(unsigned*)&h01; uh.y = *(unsigned*)&h23;
                uint2 ul; ul.x = *(unsigned*)&l01; ul.y = *(unsigned*)&l23;
                *(uint2*)(Ahi + (kb ^ xr)) = uh;
                *(uint2*)(Alo + (kb ^ xr)) = ul;
            }
            hp_s[tid] = hacc;
        }
        __syncthreads();

        // ---- dw = sigmoid(h.W2+b2); s = tm*dw ----
        if (tid < TILE_E) {
            float hsum = hp_s[4 * tid] + hp_s[4 * tid + 1] + hp_s[4 * tid + 2] + hp_s[4 * tid + 3];
            float dw = 1.f / (1.f + expf(-(hsum + b2v)));
            ss_s[tid] = tm_s[tid] * dw;
        }
        __syncthreads();

        // ---- GEMM: K and V halves, 3-pass 3xBF16, warp owns one n8 slice ----
        float aK[32], aV[32];
#pragma unroll
        for (int i = 0; i < 32; i++) { aK[i] = 0.f; aV[i] = 0.f; }
        for (int ks = 0; ks < 8; ks++) {
            uint32_t kbB = (uint32_t)(ks * 32 + mb * 16) ^ bXor;
            uint32_t bhK[2], blK[2], bhV[2], blV[2];
            ldsm2(bhK, bRowK + kbB);
            ldsm2(blK, bLoRowK + kbB);
            ldsm2(bhV, bRowV + kbB);
            ldsm2(blV, bLoRowV + kbB);
            uint32_t kbA = ((uint32_t)(ks * 32) + aKh) ^ aXor;
#pragma unroll
            for (int mt = 0; mt < 8; mt++) {
                uint32_t aoff = (uint32_t)(mt * 16) * 256u + aRowLoc + kbA;
                uint32_t ah[4], al[4];
                ldsm4(ah, smb + OFF_AHI + aoff);
                ldsm4(al, smb + OFF_ALO + aoff);
                mma16816(aK + mt * 4, ah, bhK);
                mma16816(aK + mt * 4, ah, blK);
                mma16816(aK + mt * 4, al, bhK);
                mma16816(aV + mt * 4, ah, bhV);
                mma16816(aV + mt * 4, ah, blV);
                mma16816(aV + mt * 4, al, bhV);
            }
        }
        __syncthreads();   // A tile no longer needed; KV buf aliases it

        // ---- stage K accums to smem (swizzled rows of 512B) ----
#pragma unroll
        for (int mt = 0; mt < 8; mt++) {
            int m0 = mt * 16 + r4;
            unsigned jb = (unsigned)((n0k + c2) * 4);
            char* base = smc + OFF_KV;
            *(float2*)(base + m0 * 512 + (jb ^ ((unsigned)(m0 & 31) << 4))) =
                make_float2(aK[mt * 4 + 0], aK[mt * 4 + 1]);
            int m1 = m0 + 8;
            *(float2*)(base + m1 * 512 + (jb ^ ((unsigned)(m1 & 31) << 4))) =
                make_float2(aK[mt * 4 + 2], aK[mt * 4 + 3]);
        }
        __syncthreads();

        // ---- score phase: thread covers 32 cols (2 heads) of one edge ----
        {
            int qq = wid & 3;
            int e = (wid >> 2) * 32 + lane;
            int d2 = dst_s[e];
            float sce = ss_s[e];
            bool valid = (e < cnt);
            const float* qrow = g_Q + (size_t)d2 * H;
            char* kbase = smc + OFF_KV + e * 512;
            unsigned xr = (unsigned)(e & 31) << 4;
            float s0 = 0.f, s1 = 0.f;
#pragma unroll
            for (int i = 0; i < 8; i++) {
                unsigned jb = (unsigned)(qq * 128 + i * 16);
                float4 kr = *(float4*)(kbase + (jb ^ xr));
                int j = qq * 32 + i * 4;
                float4 q4 = __ldg((const float4*)(qrow + j));
                float k0 = fmaf(kr.x, sce, bk_s[j + 0]);
                float k1 = fmaf(kr.y, sce, bk_s[j + 1]);
                float k2 = fmaf(kr.z, sce, bk_s[j + 2]);
                float k3 = fmaf(kr.w, sce, bk_s[j + 3]);
                float dp = q4.x * k0 + q4.y * k1 + q4.z * k2 + q4.w * k3;
                if (i < 4) s0 += dp; else s1 += dp;
            }
            float w0 = expf(s0 * 0.25f);
            float w1 = expf(s1 * 0.25f);
            w_sm[e * 8 + 2 * qq + 0] = w0;
            w_sm[e * 8 + 2 * qq + 1] = w1;
            if (valid) {
                float* dp = &g_denom[(size_t)d2 * 8 + 2 * qq];
                asm volatile("red.global.add.v2.f32 [%0], {%1,%2};"
                             :: "l"(dp), "f"(w0), "f"(w1) : "memory");
            }
        }
        __syncthreads();

        // ---- stage V accums to smem (same buffer) ----
#pragma unroll
        for (int mt = 0; mt < 8; mt++) {
            int m0 = mt * 16 + r4;
            unsigned jb = (unsigned)((n0v - 128 + c2) * 4);
            char* base = smc + OFF_KV;
            *(float2*)(base + m0 * 512 + (jb ^ ((unsigned)(m0 & 31) << 4))) =
                make_float2(aV[mt * 4 + 0], aV[mt * 4 + 1]);
            int m1 = m0 + 8;
            *(float2*)(base + m1 * 512 + (jb ^ ((unsigned)(m1 & 31) << 4))) =
                make_float2(aV[mt * 4 + 2], aV[mt * 4 + 3]);
        }
        __syncthreads();

        // ---- V scatter phase ----
        {
            int qq = wid & 3;
            int e = (wid >> 2) * 32 + lane;
            int d2 = dst_s[e];
            float sce = ss_s[e];
            bool valid = (e < cnt);
            char* vbase = smc + OFF_KV + e * 512;
            unsigned xr = (unsigned)(e & 31) << 4;
            float* orow = out + (size_t)d2 * H;
#pragma unroll
            for (int i = 0; i < 8; i++) {
                unsigned jb = (unsigned)(qq * 128 + i * 16);
                float4 vr = *(float4*)(vbase + (jb ^ xr));
                int j = qq * 32 + i * 4;
                float ww = w_sm[e * 8 + 2 * qq + (i >> 2)];
                float v0 = fmaf(vr.x, sce, bv_s[j + 0]) * ww;
                float v1 = fmaf(vr.y, sce, bv_s[j + 1]) * ww;
                float v2 = fmaf(vr.z, sce, bv_s[j + 2]) * ww;
                float v3 = fmaf(vr.w, sce, bv_s[j + 3]) * ww;
                if (valid)
                    asm volatile("red.global.add.v4.f32 [%0], {%1,%2,%3,%4};"
                                 :: "l"(orow + j), "f"(v0), "f"(v1), "f"(v2), "f"(v3) : "memory");
            }
        }
        __syncthreads();
    }
}

// ---------------- normalize ------------------------------------------------
__global__ void k_norm(float* __restrict__ out, int N)
{
    int idx = blockIdx.x * blockDim.x + threadIdx.x;
    if (idx >= N * H) return;
    int n = idx >> 7, jj = idx & (H - 1);
    float dnm = g_denom[n * NHEAD + (jj >> 4)];
    float v = out[idx];
    out[idx] = (dnm > 0.f) ? v / dnm : 0.f;
}

// ---------------- launch ---------------------------------------------------
extern "C" void kernel_launch(void* const* d_in, const int* in_sizes, int n_in,
                              void* d_out, int out_size)
{
    const float* x     = (const float*)d_in[0];
    const float* ts    = (const float*)d_in[1];
    const int*   src   = (const int*)  d_in[2];
    const int*   dst   = (const int*)  d_in[3];
    const int*   etyp  = (const int*)  d_in[4];
    const float* etime = (const float*)d_in[5];
    const float* rel   = (const float*)d_in[6];
    const float* Wq    = (const float*)d_in[7];
    const float* bq    = (const float*)d_in[8];
    const float* Wk    = (const float*)d_in[9];
    const float* bk    = (const float*)d_in[10];
    const float* Wv    = (const float*)d_in[11];
    const float* bv    = (const float*)d_in[12];
    const float* W1    = (const float*)d_in[13];
    const float* b1    = (const float*)d_in[14];
    const float* W2    = (const float*)d_in[15];
    const float* b2    = (const float*)d_in[16];
    const float* tcp   = (const float*)d_in[17];

    int N    = in_sizes[0] / H;
    int E    = in_sizes[2];
    int NREL = in_sizes[6] / H;
    float* out = (float*)d_out;
    int ntiles = (E + TILE_E - 1) / TILE_E;

    static int smem_set = 0;
    if (!smem_set) {
        cudaFuncSetAttribute(k_edge_mma, cudaFuncAttributeMaxDynamicSharedMemorySize, SMEM_EDGE);
        smem_set = 1;
    }

    k_init <<<2048, 256>>>(out, N, out_size);
    k_rel  <<<NREL, H>>>(rel, W1);
    k_prepw<<<256, H>>>(Wk, Wv);
    k_node <<<(N + TEN - 1) / TEN, H>>>(x, Wq, bq, W1, N);
    k_edge_mma<<<148, NT, SMEM_EDGE>>>(x, ts, src, dst, etyp, etime, rel,
                                       bk, bv, b1, W2, b2, tcp, out, E, ntiles);
    k_norm <<<(N * H + 255) / 256, 256>>>(out, N);
}